// round 11
// baseline (speedup 1.0000x reference)
#include <cuda_runtime.h>

#define W_IMG  1248
#define NROWS  768
#define SEGW   320            // outputs per warp-segment
#define NSEG   4              // 4*320 = 1280 >= 1248, tail masked
#define HALO   192
#define NT     128            // 4 warps = 4 rows per CTA (same segment)
#define C      16             // elements per thread; 192 = 12*16 exactly

__global__ __launch_bounds__(NT) void stereo_c16e_kernel(
    const float* __restrict__ L,
    const float* __restrict__ R,
    float* __restrict__ out)
{
    const int tid  = threadIdx.x;
    const int lane = tid & 31;
    const int warp = tid >> 5;
    const int row  = blockIdx.x * 4 + warp;   // 192*4 = 768 rows
    const int seg  = blockIdx.y;              // 0..3

    const float* __restrict__ r = R + (size_t)row * W_IMG;
    const float* __restrict__ l = L + (size_t)row * W_IMG;
    float* __restrict__ o = out + (size_t)row * W_IMG;

    const int u0 = lane * C;                  // local coord base (0..496)
    const int j0 = seg * SEGW - HALO + u0;    // global column of this chunk
    // whole-chunk predicates (all boundaries multiples of 16)
    const bool inr  = (j0 >= 0) && (j0 + C <= W_IMG);     // r-load validity
    const bool outv = (u0 >= HALO) && (j0 + C <= W_IMG);  // output validity

    // ---- ALL loads front-batched: 8 x LDG.128, MLP=8 ----
    float rv[C];
    if (inr) {
        #pragma unroll
        for (int v = 0; v < 4; v++)
            *(float4*)(rv + 4 * v) = *(const float4*)(r + j0 + 4 * v);
    } else {
        #pragma unroll
        for (int s = 0; s < C; s++) rv[s] = 0.f;
    }
    float lv[C];
    if (outv) {
        #pragma unroll
        for (int v = 0; v < 4; v++)
            *(float4*)(lv + 4 * v) = *(const float4*)(l + j0 + 4 * v);
    }

    // ---- serial scan of 16-chunk in local coords ----
    float lp[C], lq[C];
    float p = 0.f, q = 0.f;
    {
        const float u0f = (float)u0;
        #pragma unroll
        for (int s = 0; s < C; s++) {
            p += rv[s];
            q = fmaf(u0f + (float)s, rv[s], q);
            lp[s] = p;
            lq[s] = q;
        }
    }

    // ---- inclusive warp scan of (p, q) thread totals ----
    float vp = p, vq = q;
    #pragma unroll
    for (int off = 1; off < 32; off <<= 1) {
        float ap = __shfl_up_sync(0xffffffffu, vp, off);
        float aq = __shfl_up_sync(0xffffffffu, vq, off);
        if (lane >= off) { vp += ap; vq += aq; }
    }
    const float offp = vp - p;
    const float offq = vq - q;
    #pragma unroll
    for (int s = 0; s < C; s++) { lp[s] += offp; lq[s] += offq; }

    // ---- output stage, two batched phases to overlap shuffle latency ----
    // Phase A: all producer terms + all shuffles issued back-to-back.
    // Producer (lane-12) term T = (u_prod + 192)*lp - lq  ==  consumer's
    // (u*bp - bq). Phase B: pure FFMA/FMUL combine, no shuffles in chain.
    float bT[C];
    {
        const float cA = (float)(u0 + HALO);
        #pragma unroll
        for (int s = 0; s < C; s++) {
            float T = fmaf(cA + (float)s, lp[s], -lq[s]);
            bT[s] = __shfl_up_sync(0xffffffffu, T, 12);
        }
    }
    {
        const float cB = (float)u0;
        #pragma unroll
        for (int s = 0; s < C; s++) {
            float S = fmaf(cB + (float)s, lp[s], -lq[s]) - bT[s];
            lv[s] = lv[s] * S;
        }
    }

    if (outv) {
        #pragma unroll
        for (int v = 0; v < 4; v++)
            *(float4*)(o + j0 + 4 * v) = *(const float4*)(lv + 4 * v);
    }
}

extern "C" void kernel_launch(void* const* d_in, const int* in_sizes, int n_in,
                              void* d_out, int out_size)
{
    const float* left  = (const float*)d_in[0];
    const float* right = (const float*)d_in[1];
    float* out = (float*)d_out;
    dim3 grid(NROWS / 4, NSEG);
    stereo_c16e_kernel<<<grid, NT>>>(left, right, out);
}

// round 12
// speedup vs baseline: 1.3478x; 1.3478x over previous
#include <cuda_runtime.h>

#define W_IMG  1248
#define NROWS  768
#define SEGW   320            // outputs per warp-segment
#define NSEG   4              // 4*320 = 1280 >= 1248, tail masked
#define HALO   192
#define NT     128            // 4 warps = 4 rows per CTA (same segment)
#define C      16             // elements per thread; 192 = 12*16 exactly

__global__ __launch_bounds__(NT) void stereo_win_kernel(
    const float* __restrict__ L,
    const float* __restrict__ R,
    float* __restrict__ out)
{
    const int tid  = threadIdx.x;
    const int lane = tid & 31;
    const int warp = tid >> 5;
    const int row  = blockIdx.x * 4 + warp;   // 192*4 = 768 rows
    const int seg  = blockIdx.y;              // 0..3

    const float* __restrict__ r = R + (size_t)row * W_IMG;
    const float* __restrict__ l = L + (size_t)row * W_IMG;
    float* __restrict__ o = out + (size_t)row * W_IMG;

    const int u0 = lane * C;                  // local coord base (0..496)
    const int j0 = seg * SEGW - HALO + u0;    // global column of this chunk
    // whole-chunk predicates (all boundaries multiples of 16)
    const bool inr  = (j0 >= 0) && (j0 + C <= W_IMG);     // r-load validity
    const bool outv = (u0 >= HALO) && (j0 + C <= W_IMG);  // output validity

    // ---- ALL loads front-batched: 8 x LDG.128, MLP=8 ----
    float rv[C];
    if (inr) {
        #pragma unroll
        for (int v = 0; v < 4; v++)
            *(float4*)(rv + 4 * v) = *(const float4*)(r + j0 + 4 * v);
    } else {
        #pragma unroll
        for (int s = 0; s < C; s++) rv[s] = 0.f;
    }
    float lv[C];
    if (outv) {
        #pragma unroll
        for (int v = 0; v < 4; v++)
            *(float4*)(lv + 4 * v) = *(const float4*)(l + j0 + 4 * v);
    }

    // ---- chunk-LOCAL inclusive scan (no cross-lane offset needed) ----
    float lpl[C], lql[C];
    float p = 0.f, q = 0.f;
    {
        const float u0f = (float)u0;
        #pragma unroll
        for (int s = 0; s < C; s++) {
            p += rv[s];
            q = fmaf(u0f + (float)s, rv[s], q);
            lpl[s] = p;
            lql[s] = q;
        }
    }

    // ---- width-12 sliding-window sum of chunk totals (4-deep chain) ----
    // w12(k) = sum of p over lanes k-11..k  =  s8 + shfl_up(s4, 8)
    float s2p = p + __shfl_up_sync(0xffffffffu, p, 1);
    float s2q = q + __shfl_up_sync(0xffffffffu, q, 1);
    float s4p = s2p + __shfl_up_sync(0xffffffffu, s2p, 2);
    float s4q = s2q + __shfl_up_sync(0xffffffffu, s2q, 2);
    float s8p = s4p + __shfl_up_sync(0xffffffffu, s4p, 4);
    float s8q = s4q + __shfl_up_sync(0xffffffffu, s4q, 4);
    float w12p = s8p + __shfl_up_sync(0xffffffffu, s4p, 8);
    float w12q = s8q + __shfl_up_sync(0xffffffffu, s4q, 8);
    const float wp = w12p - p;               // lanes lane-11 .. lane-1 (full chunks)
    const float wq = w12q - p * 0.f - (w12q - (w12q - q));  // = w12q - q
    // (written explicitly below to avoid compiler confusion)
    const float wq2 = w12q - q;

    // ---- outputs: own fragment + 11 full chunks + producer suffix ----
    // Producer (lane-12) term: T = u_cons*(p - lpl[s]) - (q - lql[s]),
    // u_cons = u0_prod + 192 + s. One shuffle per s.
    {
        const float cA = (float)(u0 + HALO);  // producer-side consumer coordinate
        const float cB = (float)u0;           // own coordinate base
        #pragma unroll
        for (int s = 0; s < C; s++) {
            float dp = p - lpl[s];
            float dq = q - lql[s];
            float T  = fmaf(cA + (float)s, dp, -dq);
            float bT = __shfl_up_sync(0xffffffffu, T, 12);
            float ap = lpl[s] + wp;           // window sum of r
            float aq = lql[s] + wq2;          // window sum of j*r
            float S  = fmaf(cB + (float)s, ap, -aq) + bT;
            lv[s] = lv[s] * S;
        }
    }

    if (outv) {
        #pragma unroll
        for (int v = 0; v < 4; v++)
            *(float4*)(o + j0 + 4 * v) = *(const float4*)(lv + 4 * v);
    }
    (void)wq;
}

extern "C" void kernel_launch(void* const* d_in, const int* in_sizes, int n_in,
                              void* d_out, int out_size)
{
    const float* left  = (const float*)d_in[0];
    const float* right = (const float*)d_in[1];
    float* out = (float*)d_out;
    dim3 grid(NROWS / 4, NSEG);
    stereo_win_kernel<<<grid, NT>>>(left, right, out);
}